// round 8
// baseline (speedup 1.0000x reference)
#include <cuda_runtime.h>
#include <cuda_bf16.h>

#define BDIM   8
#define CDIM   1024
#define HWDIM  32
#define NHEAD  16
#define HD     64
#define KDIM   9216          // 1024 * 9
#define NCHUNK 288           // KDIM / 32

// ---------------- scratch (static device globals; no allocations) ----------
__device__ __nv_bfloat16 g_Bh[(size_t)24 * CDIM * KDIM];  // im2col hi
__device__ __nv_bfloat16 g_Bl[(size_t)24 * CDIM * KDIM];  // im2col lo
__device__ __nv_bfloat16 g_Wh[(size_t)3 * CDIM * KDIM];   // conv weights hi
__device__ __nv_bfloat16 g_Wl[(size_t)3 * CDIM * KDIM];   // conv weights lo
__device__ __nv_bfloat16 g_Qh[BDIM * CDIM * CDIM], g_Ql[BDIM * CDIM * CDIM];
__device__ __nv_bfloat16 g_Kh[BDIM * CDIM * CDIM], g_Kl[BDIM * CDIM * CDIM];
__device__ __nv_bfloat16 g_Vh[BDIM * CDIM * CDIM], g_Vl[BDIM * CDIM * CDIM];
__device__ __nv_bfloat16 g_AOh[BDIM * CDIM * CDIM], g_AOl[BDIM * CDIM * CDIM];
__device__ __nv_bfloat16 g_Woh[CDIM * CDIM], g_Wol[CDIM * CDIM];

// ============================= PTX helpers ==================================
__device__ __forceinline__ unsigned smem_u32(const void* p) {
    unsigned a;
    asm("{ .reg .u64 t; cvta.to.shared.u64 t, %1; cvt.u32.u64 %0, t; }"
        : "=r"(a) : "l"(p));
    return a;
}
#define CP_ASYNC16(dst, src) \
    asm volatile("cp.async.cg.shared.global [%0], [%1], 16;" :: "r"(dst), "l"(src))
#define CP_COMMIT() asm volatile("cp.async.commit_group;" ::: "memory")
#define CP_WAIT1()  asm volatile("cp.async.wait_group 1;" ::: "memory")

__device__ __forceinline__ void mma_bf16(float& c0, float& c1, float& c2, float& c3,
                                         unsigned a0, unsigned a1, unsigned a2, unsigned a3,
                                         unsigned b0, unsigned b1) {
    asm volatile(
        "mma.sync.aligned.m16n8k16.row.col.f32.bf16.bf16.f32 "
        "{%0,%1,%2,%3}, {%4,%5,%6,%7}, {%8,%9}, {%0,%1,%2,%3};"
        : "+f"(c0), "+f"(c1), "+f"(c2), "+f"(c3)
        : "r"(a0), "r"(a1), "r"(a2), "r"(a3), "r"(b0), "r"(b1));
}
#define LDSM4(r, a) \
    asm volatile("ldmatrix.sync.aligned.m8n8.x4.shared.b16 {%0,%1,%2,%3}, [%4];" \
        : "=r"((r)[0]), "=r"((r)[1]), "=r"((r)[2]), "=r"((r)[3]) : "r"(a))
#define LDSM4T(r, a) \
    asm volatile("ldmatrix.sync.aligned.m8n8.x4.trans.shared.b16 {%0,%1,%2,%3}, [%4];" \
        : "=r"((r)[0]), "=r"((r)[1]), "=r"((r)[2]), "=r"((r)[3]) : "r"(a))

// ============================================================================
// Weight split: fp32 -> bf16 hi/lo (conv weights + Wo)
// ============================================================================
__global__ __launch_bounds__(256)
void wsplit_kernel(const float* __restrict__ Wq, const float* __restrict__ Wk,
                   const float* __restrict__ Wv, const float* __restrict__ Wo)
{
    const int tensor = blockIdx.y;
    const float* W;
    __nv_bfloat162 *Wh2, *Wl2;
    size_t n2;
    if (tensor < 3) {
        W = (tensor == 0) ? Wq : (tensor == 1) ? Wk : Wv;
        Wh2 = (__nv_bfloat162*)(g_Wh + (size_t)tensor * CDIM * KDIM);
        Wl2 = (__nv_bfloat162*)(g_Wl + (size_t)tensor * CDIM * KDIM);
        n2 = (size_t)CDIM * KDIM / 2;
    } else {
        W = Wo;
        Wh2 = (__nv_bfloat162*)g_Woh;
        Wl2 = (__nv_bfloat162*)g_Wol;
        n2 = (size_t)CDIM * CDIM / 2;
    }
    const float2* W2 = (const float2*)W;
    const size_t stride = (size_t)gridDim.x * 256;
    for (size_t i = (size_t)blockIdx.x * 256 + threadIdx.x; i < n2; i += stride) {
        float2 v = W2[i];
        __nv_bfloat162 h = __floats2bfloat162_rn(v.x, v.y);
        __nv_bfloat162 l = __floats2bfloat162_rn(v.x - __low2float(h),
                                                 v.y - __high2float(h));
        Wh2[i] = h; Wl2[i] = l;
    }
}

// ============================================================================
// im2col + bf16 split, k-contiguous coalesced stores.
// ============================================================================
__global__ __launch_bounds__(256)
void im2col_kernel(const float* __restrict__ xq, const float* __restrict__ xk,
                   const float* __restrict__ xv)
{
    const int pg  = blockIdx.x;
    const int icg = blockIdx.y;
    const int tb  = blockIdx.z;
    const int tensor = tb >> 3, b = tb & 7;
    const float* x = (tensor == 0) ? xq : (tensor == 1) ? xk : xv;

    const int h0  = pg * 4;
    const int ic0 = icg * 32;

    __shared__ float sx[32][6][34];
    const int t = threadIdx.x;
    for (int idx = t; idx < 32 * 6 * 34; idx += 256) {
        int ic  = idx / 204;
        int rem = idx - ic * 204;
        int r   = rem / 34;
        int cc  = rem - r * 34;
        int gh  = h0 + r - 1;
        int gw  = cc - 1;
        float v = 0.f;
        if ((unsigned)gh < 32u && (unsigned)gw < 32u)
            v = x[((size_t)b * CDIM + ic0 + ic) * 1024 + gh * 32 + gw];
        sx[ic][r][cc] = v;
    }
    __syncthreads();

    __nv_bfloat16* dh = g_Bh + (size_t)tb * CDIM * KDIM;
    __nv_bfloat16* dl = g_Bl + (size_t)tb * CDIM * KDIM;

    for (int idx = t; idx < 128 * 288; idx += 256) {
        int pl = idx / 288;
        int kl = idx - pl * 288;
        int ic = kl / 9;
        int tap = kl - ic * 9;
        int ph = pl >> 5, w = pl & 31;
        float v = sx[ic][ph + tap / 3][w + tap % 3];
        __nv_bfloat16 h = __float2bfloat16(v);
        size_t off = (size_t)(pg * 128 + pl) * KDIM + ic0 * 9 + kl;
        dh[off] = h;
        dl[off] = __float2bfloat16(v - __bfloat162float(h));
    }
}

// ============================================================================
// GEMM core: CTA tile 128(M) x 256(N), K chunk 32, warp tile 64x64 (2x4 grid).
// smem per stage: Ah,Al (128x32), Bh,Bl (256x32), 80B row stride.
// ============================================================================
#define TSB    80
#define A_TILE (128 * TSB)             // 10240
#define B_TILE (256 * TSB)             // 20480
#define STAGEB (2 * A_TILE + 2 * B_TILE)  // 61440
#define GSMEM  (2 * STAGEB)            // 122880

__device__ __forceinline__ void stage2(
    unsigned sb, int buf,
    const __nv_bfloat16* __restrict__ Ah, const __nv_bfloat16* __restrict__ Al,
    const __nv_bfloat16* __restrict__ Bh, const __nv_bfloat16* __restrict__ Bl,
    int k0, int tid, int kdim)
{
    const unsigned base = sb + buf * STAGEB;
    #pragma unroll
    for (int t = 0; t < 2; t++) {
        const __nv_bfloat16* s = t ? Al : Ah;
        #pragma unroll
        for (int i = tid; i < 512; i += 256) {
            int row = i >> 2, c = i & 3;
            CP_ASYNC16(base + t * A_TILE + row * TSB + c * 16,
                       s + (size_t)row * kdim + k0 + c * 8);
        }
    }
    #pragma unroll
    for (int t = 0; t < 2; t++) {
        const __nv_bfloat16* s = t ? Bl : Bh;
        #pragma unroll
        for (int i = tid; i < 1024; i += 256) {
            int row = i >> 2, c = i & 3;
            CP_ASYNC16(base + 2 * A_TILE + t * B_TILE + row * TSB + c * 16,
                       s + (size_t)row * kdim + k0 + c * 8);
        }
    }
}

__device__ __forceinline__ void gemm_chunk256(unsigned base, int wm, int wn,
                                              int lane, float acc[4][8][4])
{
    const unsigned ah_ = base;
    const unsigned al_ = base + A_TILE;
    const unsigned bh_ = base + 2 * A_TILE;
    const unsigned bl_ = base + 2 * A_TILE + B_TILE;
    const int q = lane >> 3, rr = lane & 7;
    const int lrow = (q & 1) * 8 + rr;
    const int kc8  = (q >> 1) * 8;

    #pragma unroll
    for (int s = 0; s < 2; s++) {
        unsigned aH[4][4], aL[4][4];
        #pragma unroll
        for (int mt = 0; mt < 4; mt++) {
            unsigned ro = (wm * 64 + mt * 16 + lrow) * TSB + (s * 16 + kc8) * 2;
            LDSM4(aH[mt], ah_ + ro);
            LDSM4(aL[mt], al_ + ro);
        }
        #pragma unroll
        for (int np = 0; np < 4; np++) {
            unsigned bro = (wn * 64 + np * 16 + lrow) * TSB + (s * 16 + kc8) * 2;
            unsigned bH[4], bL[4];
            LDSM4(bH, bh_ + bro);
            LDSM4(bL, bl_ + bro);
            #pragma unroll
            for (int mt = 0; mt < 4; mt++) {
                #pragma unroll
                for (int o = 0; o < 2; o++) {
                    float* c4 = acc[mt][np * 2 + o];
                    mma_bf16(c4[0], c4[1], c4[2], c4[3],
                             aH[mt][0], aH[mt][1], aH[mt][2], aH[mt][3],
                             bH[o], bH[2 + o]);
                    mma_bf16(c4[0], c4[1], c4[2], c4[3],
                             aH[mt][0], aH[mt][1], aH[mt][2], aH[mt][3],
                             bL[o], bL[2 + o]);
                    mma_bf16(c4[0], c4[1], c4[2], c4[3],
                             aL[mt][0], aL[mt][1], aL[mt][2], aL[mt][3],
                             bH[o], bH[2 + o]);
                }
            }
        }
    }
}

// ============================================================================
// Conv GEMM: 128 o-ch x 256 p per CTA. Epilogue writes bf16 hi/lo Q/K/V.
// ============================================================================
__global__ __launch_bounds__(256)
void conv_mma_kernel(const float* __restrict__ bq, const float* __restrict__ bk,
                     const float* __restrict__ bv)
{
    extern __shared__ __align__(128) char smem[];
    const int tid = threadIdx.x;
    const int wid = tid >> 5, lane = tid & 31;
    const int wm = wid & 1, wn = wid >> 1;

    const int tb = blockIdx.z;
    const int tensor = tb >> 3, b = tb & 7;
    const float* bias = (tensor == 0) ? bq : (tensor == 1) ? bk : bv;
    __nv_bfloat16* outh = (tensor == 0) ? g_Qh : (tensor == 1) ? g_Kh : g_Vh;
    __nv_bfloat16* outl = (tensor == 0) ? g_Ql : (tensor == 1) ? g_Kl : g_Vl;

    const int o0 = blockIdx.x * 128;
    const int p0 = blockIdx.y * 256;

    const __nv_bfloat16* Ah = g_Wh + (size_t)tensor * CDIM * KDIM + (size_t)o0 * KDIM;
    const __nv_bfloat16* Al = g_Wl + (size_t)tensor * CDIM * KDIM + (size_t)o0 * KDIM;
    const __nv_bfloat16* Bh = g_Bh + (size_t)tb * CDIM * KDIM + (size_t)p0 * KDIM;
    const __nv_bfloat16* Bl = g_Bl + (size_t)tb * CDIM * KDIM + (size_t)p0 * KDIM;

    const unsigned sb = smem_u32(smem);

    float acc[4][8][4];
    #pragma unroll
    for (int i = 0; i < 4; i++)
        #pragma unroll
        for (int j = 0; j < 8; j++)
            #pragma unroll
            for (int r = 0; r < 4; r++) acc[i][j][r] = 0.f;

    stage2(sb, 0, Ah, Al, Bh, Bl, 0, tid, KDIM);
    CP_COMMIT();

    for (int c = 0; c < NCHUNK; c++) {
        if (c + 1 < NCHUNK)
            stage2(sb, (c + 1) & 1, Ah, Al, Bh, Bl, (c + 1) * 32, tid, KDIM);
        CP_COMMIT();
        CP_WAIT1();
        __syncthreads();
        gemm_chunk256(sb + (c & 1) * STAGEB, wm, wn, lane, acc);
        __syncthreads();
    }

    #pragma unroll
    for (int mt = 0; mt < 4; mt++) {
        #pragma unroll
        for (int rr = 0; rr < 2; rr++) {
            int row = wm * 64 + mt * 16 + (lane >> 2) + rr * 8;
            float bv_ = bias[o0 + row];
            size_t ro = ((size_t)b * CDIM + o0 + row) * CDIM + p0;
            #pragma unroll
            for (int nt = 0; nt < 8; nt++) {
                int col = wn * 64 + nt * 8 + (lane & 3) * 2;
                float v0 = acc[mt][nt][rr * 2 + 0] + bv_;
                float v1 = acc[mt][nt][rr * 2 + 1] + bv_;
                __nv_bfloat162 h2 = __floats2bfloat162_rn(v0, v1);
                __nv_bfloat162 l2 = __floats2bfloat162_rn(v0 - __low2float(h2),
                                                          v1 - __high2float(h2));
                *(__nv_bfloat162*)(outh + ro + col) = h2;
                *(__nv_bfloat162*)(outl + ro + col) = l2;
            }
        }
    }
}

// ============================================================================
// Projection GEMM: 128 c x 256 m per CTA, K=1024, fp32 out + bias.
// ============================================================================
__global__ __launch_bounds__(256)
void proj_mma_kernel(const float* __restrict__ bo, float* __restrict__ out)
{
    extern __shared__ __align__(128) char smem[];
    const int tid = threadIdx.x;
    const int wid = tid >> 5, lane = tid & 31;
    const int wm = wid & 1, wn = wid >> 1;

    const int b  = blockIdx.z;
    const int c0 = blockIdx.x * 128;
    const int m0 = blockIdx.y * 256;

    const __nv_bfloat16* Ah = g_AOh + ((size_t)b * CDIM + c0) * CDIM;
    const __nv_bfloat16* Al = g_AOl + ((size_t)b * CDIM + c0) * CDIM;
    const __nv_bfloat16* Bh = g_Woh + (size_t)m0 * CDIM;
    const __nv_bfloat16* Bl = g_Wol + (size_t)m0 * CDIM;

    const unsigned sb = smem_u32(smem);

    float acc[4][8][4];
    #pragma unroll
    for (int i = 0; i < 4; i++)
        #pragma unroll
        for (int j = 0; j < 8; j++)
            #pragma unroll
            for (int r = 0; r < 4; r++) acc[i][j][r] = 0.f;

    stage2(sb, 0, Ah, Al, Bh, Bl, 0, tid, CDIM);
    CP_COMMIT();

    for (int c = 0; c < 32; c++) {
        if (c + 1 < 32)
            stage2(sb, (c + 1) & 1, Ah, Al, Bh, Bl, (c + 1) * 32, tid, CDIM);
        CP_COMMIT();
        CP_WAIT1();
        __syncthreads();
        gemm_chunk256(sb + (c & 1) * STAGEB, wm, wn, lane, acc);
        __syncthreads();
    }

    #pragma unroll
    for (int mt = 0; mt < 4; mt++) {
        #pragma unroll
        for (int rr = 0; rr < 2; rr++) {
            int row = wm * 64 + mt * 16 + (lane >> 2) + rr * 8;
            float* orow = out + ((size_t)b * CDIM + c0 + row) * CDIM + m0;
            #pragma unroll
            for (int nt = 0; nt < 8; nt++) {
                int col = wn * 64 + nt * 8 + (lane & 3) * 2;
                float2 vv;
                vv.x = acc[mt][nt][rr * 2 + 0] + bo[m0 + col];
                vv.y = acc[mt][nt][rr * 2 + 1] + bo[m0 + col + 1];
                *(float2*)(orow + col) = vv;
            }
        }
    }
}

// ============================================================================
// Attention via mma.sync, split bf16, flash-style online softmax (unchanged).
// ============================================================================
#define ATS      144
#define ATT_QL   18432
#define ATT_BUF  36864
#define ATT_BUFSZ 36864
#define ATT_SMEM (ATT_BUF + 2 * ATT_BUFSZ)

__global__ __launch_bounds__(256)
void attn_mma_kernel(const int* __restrict__ mask)
{
    extern __shared__ __align__(128) char sm[];
    const unsigned sb = smem_u32(sm);
    const int tid = threadIdx.x, wid = tid >> 5, lane = tid & 31;
    const int bh = blockIdx.y, b = bh >> 4, head = bh & 15, hb = head * HD;
    const int t0 = blockIdx.x * 128;

    const size_t rowbase = (size_t)b * CDIM * CDIM + hb;

    for (int i = tid; i < 2048; i += 256) {
        int t = i >> 10, r = (i >> 3) & 127, c = i & 7;
        const __nv_bfloat16* src = (t ? g_Ql : g_Qh) + rowbase + (size_t)(t0 + r) * CDIM + c * 8;
        CP_ASYNC16(sb + t * ATT_QL + r * ATS + c * 16, src);
    }
    for (int i = tid; i < 2048; i += 256) {
        int t = i >> 9, r = (i >> 3) & 63, c = i & 7;
        const __nv_bfloat16* base = (t == 0) ? g_Kh : (t == 1) ? g_Kl
                                  : (t == 2) ? g_Vh : g_Vl;
        CP_ASYNC16(sb + ATT_BUF + t * 9216 + r * ATS + c * 16,
                   base + rowbase + (size_t)r * CDIM + c * 8);
    }
    CP_COMMIT();

    float oacc[8][4];
    #pragma unroll
    for (int i = 0; i < 8; i++)
        #pragma unroll
        for (int j = 0; j < 4; j++) oacc[i][j] = 0.f;
    float mrun0 = -1e30f, mrun1 = -1e30f, lrun0 = 0.f, lrun1 = 0.f;

    const int qrow = wid * 16 + (lane & 15);
    const unsigned qcoloff = ((lane >> 4) & 1) * 16;
    const unsigned kro = ((lane >> 4) & 1) * 8 + (lane & 7);
    const unsigned kco = ((lane >> 3) & 1) * 16;
    const unsigned vro = ((lane >> 3) & 1) * 8 + (lane & 7);
    const unsigned vco = ((lane >> 4) & 1) * 16;

    for (int s = 0; s < 16; s++) {
        __syncthreads();
        if (s + 1 < 16) {
            unsigned bufb = sb + ATT_BUF + ((s + 1) & 1) * ATT_BUFSZ;
            for (int i = tid; i < 2048; i += 256) {
                int t = i >> 9, r = (i >> 3) & 63, c = i & 7;
                const __nv_bfloat16* base = (t == 0) ? g_Kh : (t == 1) ? g_Kl
                                          : (t == 2) ? g_Vh : g_Vl;
                CP_ASYNC16(bufb + t * 9216 + r * ATS + c * 16,
                           base + rowbase + (size_t)((s + 1) * 64 + r) * CDIM + c * 8);
            }
        }
        CP_COMMIT();
        CP_WAIT1();
        __syncthreads();

        const unsigned kb = sb + ATT_BUF + (s & 1) * ATT_BUFSZ;

        float sacc[8][4];
        #pragma unroll
        for (int i = 0; i < 8; i++)
            #pragma unroll
            for (int j = 0; j < 4; j++) sacc[i][j] = 0.f;

        #pragma unroll
        for (int ks = 0; ks < 4; ks++) {
            unsigned qh[4], ql[4];
            unsigned qa = sb + qrow * ATS + ks * 32 + qcoloff;
            LDSM4(qh, qa);
            LDSM4(ql, qa + ATT_QL);
            #pragma unroll
            for (int gg = 0; gg < 4; gg++) {
                unsigned ka = kb + (gg * 16 + kro) * ATS + ks * 32 + kco;
                unsigned kh[4], kl[4];
                LDSM4(kh, ka);
                LDSM4(kl, ka + 9216);
                float* cA = sacc[2 * gg];
                float* cB = sacc[2 * gg + 1];
                mma_bf16(cA[0], cA[1], cA[2], cA[3], qh[0], qh[1], qh[2], qh[3], kh[0], kh[1]);
                mma_bf16(cA[0], cA[1], cA[2], cA[3], qh[0], qh[1], qh[2], qh[3], kl[0], kl[1]);
                mma_bf16(cA[0], cA[1], cA[2], cA[3], ql[0], ql[1], ql[2], ql[3], kh[0], kh[1]);
                mma_bf16(cB[0], cB[1], cB[2], cB[3], qh[0], qh[1], qh[2], qh[3], kh[2], kh[3]);
                mma_bf16(cB[0], cB[1], cB[2], cB[3], qh[0], qh[1], qh[2], qh[3], kl[2], kl[3]);
                mma_bf16(cB[0], cB[1], cB[2], cB[3], ql[0], ql[1], ql[2], ql[3], kh[2], kh[3]);
            }
        }

        const int r0 = t0 + wid * 16 + (lane >> 2);
        const int* mp = mask + (size_t)b * CDIM * CDIM + (size_t)r0 * CDIM
                        + s * 64 + (lane & 3) * 2;
        float mx0 = -1e30f, mx1 = -1e30f;
        #pragma unroll
        for (int nt = 0; nt < 8; nt++) {
            int2 m0 = *(const int2*)(mp + nt * 8);
            int2 m1 = *(const int2*)(mp + 8 * CDIM + nt * 8);
            float v0 = sacc[nt][0] * 0.125f; if (m0.x == 0) v0 = -1e9f;
            float v1 = sacc[nt][1] * 0.125f; if (m0.y == 0) v1 = -1e9f;
            float v2 = sacc[nt][2] * 0.125f; if (m1.x == 0) v2 = -1e9f;
            float v3 = sacc[nt][3] * 0.125f; if (m1.y == 0) v3 = -1e9f;
            sacc[nt][0] = v0; sacc[nt][1] = v1; sacc[nt][2] = v2; sacc[nt][3] = v3;
            mx0 = fmaxf(mx0, fmaxf(v0, v1));
            mx1 = fmaxf(mx1, fmaxf(v2, v3));
        }
        mx0 = fmaxf(mx0, __shfl_xor_sync(0xFFFFFFFFu, mx0, 1));
        mx0 = fmaxf(mx0, __shfl_xor_sync(0xFFFFFFFFu, mx0, 2));
        mx1 = fmaxf(mx1, __shfl_xor_sync(0xFFFFFFFFu, mx1, 1));
        mx1 = fmaxf(mx1, __shfl_xor_sync(0xFFFFFFFFu, mx1, 2));

        float mn0 = fmaxf(mrun0, mx0), mn1 = fmaxf(mrun1, mx1);
        float f0 = __expf(mrun0 - mn0), f1 = __expf(mrun1 - mn1);
        mrun0 = mn0; mrun1 = mn1;

        float sum0 = 0.f, sum1 = 0.f;
        #pragma unroll
        for (int nt = 0; nt < 8; nt++) {
            float p0 = __expf(sacc[nt][0] - mn0);
            float p1 = __expf(sacc[nt][1] - mn0);
            float p2 = __expf(sacc[nt][2] - mn1);
            float p3 = __expf(sacc[nt][3] - mn1);
            sacc[nt][0] = p0; sacc[nt][1] = p1; sacc[nt][2] = p2; sacc[nt][3] = p3;
            sum0 += p0 + p1; sum1 += p2 + p3;
        }
        sum0 += __shfl_xor_sync(0xFFFFFFFFu, sum0, 1);
        sum0 += __shfl_xor_sync(0xFFFFFFFFu, sum0, 2);
        sum1 += __shfl_xor_sync(0xFFFFFFFFu, sum1, 1);
        sum1 += __shfl_xor_sync(0xFFFFFFFFu, sum1, 2);
        lrun0 = lrun0 * f0 + sum0;
        lrun1 = lrun1 * f1 + sum1;

        #pragma unroll
        for (int nt = 0; nt < 8; nt++) {
            oacc[nt][0] *= f0; oacc[nt][1] *= f0;
            oacc[nt][2] *= f1; oacc[nt][3] *= f1;
        }

        #pragma unroll
        for (int ks = 0; ks < 4; ks++) {
            unsigned ah[4], al[4];
            #pragma unroll
            for (int h2i = 0; h2i < 2; h2i++) {
                float x0 = sacc[2 * ks + h2i][0], x1 = sacc[2 * ks + h2i][1];
                float x2 = sacc[2 * ks + h2i][2], x3 = sacc[2 * ks + h2i][3];
                __nv_bfloat162 hA = __floats2bfloat162_rn(x0, x1);
                __nv_bfloat162 hB = __floats2bfloat162_rn(x2, x3);
                ah[0 + 2 * h2i] = *(unsigned*)&hA;
                ah[1 + 2 * h2i] = *(unsigned*)&hB;
                __nv_bfloat162 lA = __floats2bfloat162_rn(x0 - __low2float(hA),
                                                          x1 - __high2float(hA));
                __nv_bfloat162 lB = __floats2bfloat162_rn(x2 - __low2float(hB),
                                                          x3 - __high2float(hB));
                al[0 + 2 * h2i] = *(unsigned*)&lA;
                al[1 + 2 * h2i] = *(unsigned*)&lB;
            }
            unsigned a0 = ah[0], a1 = ah[1], a2 = ah[2], a3 = ah[3];
            unsigned b0 = al[0], b1 = al[1], b2 = al[2], b3 = al[3];
            #pragma unroll
            for (int gg = 0; gg < 4; gg++) {
                unsigned va = kb + 2 * 9216 + (ks * 16 + vro) * ATS + gg * 32 + vco;
                unsigned vh[4], vl[4];
                LDSM4T(vh, va);
                LDSM4T(vl, va + 9216);
                float* cA = oacc[2 * gg];
                float* cB = oacc[2 * gg + 1];
                mma_bf16(cA[0], cA[1], cA[2], cA[3], a0, a1, a2, a3, vh[0], vh[1]);
                mma_bf16(cA[0], cA[1], cA[2], cA[3], a0, a1, a2, a3, vl[0], vl[1]);
                mma_bf16(cA[0], cA[1], cA[2], cA[3], b0, b1, b2, b3, vh[0], vh[1]);
                mma_bf16(cB[0], cB[1], cB[2], cB[3], a0, a1, a2, a3, vh[2], vh[3]);
                mma_bf16(cB[0], cB[1], cB[2], cB[3], a0, a1, a2, a3, vl[2], vl[3]);
                mma_bf16(cB[0], cB[1], cB[2], cB[3], b0, b1, b2, b3, vh[2], vh[3]);
            }
        }
    }

    float li0 = 1.f / lrun0, li1 = 1.f / lrun1;
    const int r0g = t0 + wid * 16 + (lane >> 2);
    const size_t ob = (size_t)b * CDIM * CDIM + hb;
    #pragma unroll
    for (int nt = 0; nt < 8; nt++) {
        int col = nt * 8 + (lane & 3) * 2;
        float v0 = oacc[nt][0] * li0, v1 = oacc[nt][1] * li0;
        __nv_bfloat162 h2 = __floats2bfloat162_rn(v0, v1);
        __nv_bfloat162 l2 = __floats2bfloat162_rn(v0 - __low2float(h2),
                                                  v1 - __high2float(h2));
        *(__nv_bfloat162*)(g_AOh + ob + (size_t)r0g * CDIM + col) = h2;
        *(__nv_bfloat162*)(g_AOl + ob + (size_t)r0g * CDIM + col) = l2;
        float v2 = oacc[nt][2] * li1, v3 = oacc[nt][3] * li1;
        __nv_bfloat162 h3 = __floats2bfloat162_rn(v2, v3);
        __nv_bfloat162 l3 = __floats2bfloat162_rn(v2 - __low2float(h3),
                                                  v3 - __high2float(h3));
        *(__nv_bfloat162*)(g_AOh + ob + (size_t)(r0g + 8) * CDIM + col) = h3;
        *(__nv_bfloat162*)(g_AOl + ob + (size_t)(r0g + 8) * CDIM + col) = l3;
    }
}

// ============================================================================
extern "C" void kernel_launch(void* const* d_in, const int* in_sizes, int n_in,
                              void* d_out, int out_size)
{
    const float* q    = (const float*)d_in[0];
    const float* k    = (const float*)d_in[1];
    const float* v    = (const float*)d_in[2];
    const float* Wq   = (const float*)d_in[3];
    const float* bq   = (const float*)d_in[4];
    const float* Wk   = (const float*)d_in[5];
    const float* bk   = (const float*)d_in[6];
    const float* Wv   = (const float*)d_in[7];
    const float* bv   = (const float*)d_in[8];
    const float* Wo   = (const float*)d_in[9];
    const float* bo   = (const float*)d_in[10];
    const int*   mask = (const int*)d_in[11];

    // 1) split weights (conv + Wo)
    wsplit_kernel<<<dim3(1024, 4), 256>>>(Wq, Wk, Wv, Wo);

    // 2) im2col with bf16 split
    im2col_kernel<<<dim3(8, 32, 24), 256>>>(q, k, v);

    // 3) conv GEMM 128x256 tiles
    cudaFuncSetAttribute(conv_mma_kernel,
                         cudaFuncAttributeMaxDynamicSharedMemorySize, GSMEM);
    conv_mma_kernel<<<dim3(8, 4, 24), 256, GSMEM>>>(bq, bk, bv);

    // 4) attention
    cudaFuncSetAttribute(attn_mma_kernel,
                         cudaFuncAttributeMaxDynamicSharedMemorySize, ATT_SMEM);
    attn_mma_kernel<<<dim3(8, 128), 256, ATT_SMEM>>>(mask);

    // 5) projection GEMM 128x256 tiles
    cudaFuncSetAttribute(proj_mma_kernel,
                         cudaFuncAttributeMaxDynamicSharedMemorySize, GSMEM);
    proj_mma_kernel<<<dim3(8, 4, 8), 256, GSMEM>>>(bo, (float*)d_out);
}

// round 9
// speedup vs baseline: 1.0755x; 1.0755x over previous
#include <cuda_runtime.h>
#include <cuda_bf16.h>

#define BDIM   8
#define CDIM   1024
#define HWDIM  32
#define NHEAD  16
#define HD     64
#define KDIM   9216          // 1024 * 9
#define NCHUNK 288           // KDIM / 32

// ---------------- scratch (static device globals; no allocations) ----------
__device__ __nv_bfloat16 g_Bh[(size_t)24 * CDIM * KDIM];  // im2col hi
__device__ __nv_bfloat16 g_Bl[(size_t)24 * CDIM * KDIM];  // im2col lo
__device__ __nv_bfloat16 g_Wh[(size_t)3 * CDIM * KDIM];   // conv weights hi
__device__ __nv_bfloat16 g_Wl[(size_t)3 * CDIM * KDIM];   // conv weights lo
__device__ __nv_bfloat16 g_Qh[BDIM * CDIM * CDIM], g_Ql[BDIM * CDIM * CDIM];
__device__ __nv_bfloat16 g_Kh[BDIM * CDIM * CDIM], g_Kl[BDIM * CDIM * CDIM];
__device__ __nv_bfloat16 g_Vh[BDIM * CDIM * CDIM], g_Vl[BDIM * CDIM * CDIM];
__device__ __nv_bfloat16 g_AOh[BDIM * CDIM * CDIM], g_AOl[BDIM * CDIM * CDIM];
__device__ __nv_bfloat16 g_Woh[CDIM * CDIM], g_Wol[CDIM * CDIM];

// ============================= PTX helpers ==================================
__device__ __forceinline__ unsigned smem_u32(const void* p) {
    unsigned a;
    asm("{ .reg .u64 t; cvta.to.shared.u64 t, %1; cvt.u32.u64 %0, t; }"
        : "=r"(a) : "l"(p));
    return a;
}
#define CP_ASYNC16(dst, src) \
    asm volatile("cp.async.cg.shared.global [%0], [%1], 16;" :: "r"(dst), "l"(src))
#define CP_COMMIT() asm volatile("cp.async.commit_group;" ::: "memory")
#define CP_WAIT1()  asm volatile("cp.async.wait_group 1;" ::: "memory")
#define CP_WAIT2()  asm volatile("cp.async.wait_group 2;" ::: "memory")

__device__ __forceinline__ void mma_bf16(float& c0, float& c1, float& c2, float& c3,
                                         unsigned a0, unsigned a1, unsigned a2, unsigned a3,
                                         unsigned b0, unsigned b1) {
    asm volatile(
        "mma.sync.aligned.m16n8k16.row.col.f32.bf16.bf16.f32 "
        "{%0,%1,%2,%3}, {%4,%5,%6,%7}, {%8,%9}, {%0,%1,%2,%3};"
        : "+f"(c0), "+f"(c1), "+f"(c2), "+f"(c3)
        : "r"(a0), "r"(a1), "r"(a2), "r"(a3), "r"(b0), "r"(b1));
}
#define LDSM4(r, a) \
    asm volatile("ldmatrix.sync.aligned.m8n8.x4.shared.b16 {%0,%1,%2,%3}, [%4];" \
        : "=r"((r)[0]), "=r"((r)[1]), "=r"((r)[2]), "=r"((r)[3]) : "r"(a))
#define LDSM4T(r, a) \
    asm volatile("ldmatrix.sync.aligned.m8n8.x4.trans.shared.b16 {%0,%1,%2,%3}, [%4];" \
        : "=r"((r)[0]), "=r"((r)[1]), "=r"((r)[2]), "=r"((r)[3]) : "r"(a))

// ============================================================================
// Weight split: fp32 -> bf16 hi/lo (conv weights + Wo)
// ============================================================================
__global__ __launch_bounds__(256)
void wsplit_kernel(const float* __restrict__ Wq, const float* __restrict__ Wk,
                   const float* __restrict__ Wv, const float* __restrict__ Wo)
{
    const int tensor = blockIdx.y;
    const float* W;
    __nv_bfloat162 *Wh2, *Wl2;
    size_t n2;
    if (tensor < 3) {
        W = (tensor == 0) ? Wq : (tensor == 1) ? Wk : Wv;
        Wh2 = (__nv_bfloat162*)(g_Wh + (size_t)tensor * CDIM * KDIM);
        Wl2 = (__nv_bfloat162*)(g_Wl + (size_t)tensor * CDIM * KDIM);
        n2 = (size_t)CDIM * KDIM / 2;
    } else {
        W = Wo;
        Wh2 = (__nv_bfloat162*)g_Woh;
        Wl2 = (__nv_bfloat162*)g_Wol;
        n2 = (size_t)CDIM * CDIM / 2;
    }
    const float2* W2 = (const float2*)W;
    const size_t stride = (size_t)gridDim.x * 256;
    for (size_t i = (size_t)blockIdx.x * 256 + threadIdx.x; i < n2; i += stride) {
        float2 v = W2[i];
        __nv_bfloat162 h = __floats2bfloat162_rn(v.x, v.y);
        __nv_bfloat162 l = __floats2bfloat162_rn(v.x - __low2float(h),
                                                 v.y - __high2float(h));
        Wh2[i] = h; Wl2[i] = l;
    }
}

// ============================================================================
// im2col + bf16 split, k-contiguous coalesced stores.
// ============================================================================
__global__ __launch_bounds__(256)
void im2col_kernel(const float* __restrict__ xq, const float* __restrict__ xk,
                   const float* __restrict__ xv)
{
    const int pg  = blockIdx.x;
    const int icg = blockIdx.y;
    const int tb  = blockIdx.z;
    const int tensor = tb >> 3, b = tb & 7;
    const float* x = (tensor == 0) ? xq : (tensor == 1) ? xk : xv;

    const int h0  = pg * 4;
    const int ic0 = icg * 32;

    __shared__ float sx[32][6][34];
    const int t = threadIdx.x;
    for (int idx = t; idx < 32 * 6 * 34; idx += 256) {
        int ic  = idx / 204;
        int rem = idx - ic * 204;
        int r   = rem / 34;
        int cc  = rem - r * 34;
        int gh  = h0 + r - 1;
        int gw  = cc - 1;
        float v = 0.f;
        if ((unsigned)gh < 32u && (unsigned)gw < 32u)
            v = x[((size_t)b * CDIM + ic0 + ic) * 1024 + gh * 32 + gw];
        sx[ic][r][cc] = v;
    }
    __syncthreads();

    __nv_bfloat16* dh = g_Bh + (size_t)tb * CDIM * KDIM;
    __nv_bfloat16* dl = g_Bl + (size_t)tb * CDIM * KDIM;

    for (int idx = t; idx < 128 * 288; idx += 256) {
        int pl = idx / 288;
        int kl = idx - pl * 288;
        int ic = kl / 9;
        int tap = kl - ic * 9;
        int ph = pl >> 5, w = pl & 31;
        float v = sx[ic][ph + tap / 3][w + tap % 3];
        __nv_bfloat16 h = __float2bfloat16(v);
        size_t off = (size_t)(pg * 128 + pl) * KDIM + ic0 * 9 + kl;
        dh[off] = h;
        dl[off] = __float2bfloat16(v - __bfloat162float(h));
    }
}

// ============================================================================
// GEMM staging: 4 tiles x 128 rows x 32 k per stage, 4-stage ring.
// ============================================================================
#define TSB   80
#define TILEB (128 * TSB)              // 10240 bytes per tile
#define BUFB  (4 * TILEB)              // 40960 bytes per stage
#define NSTAGE 4
#define GSMEM  (NSTAGE * BUFB)         // 163840

__device__ __forceinline__ void stage_chunk(
    unsigned sb, int buf,
    const __nv_bfloat16* __restrict__ Ah, const __nv_bfloat16* __restrict__ Al,
    const __nv_bfloat16* __restrict__ Bh, const __nv_bfloat16* __restrict__ Bl,
    int k0, int tid, int kdim)
{
    const __nv_bfloat16* srcs[4] = {Ah, Al, Bh, Bl};
    #pragma unroll
    for (int tt = 0; tt < 4; tt++) {
        const __nv_bfloat16* s = srcs[tt];
        #pragma unroll 2
        for (int i = tid; i < 512; i += 256) {
            int row = i >> 2, c = i & 3;
            unsigned dst = sb + buf * BUFB + tt * TILEB + row * TSB + c * 16;
            const void* src = s + (size_t)row * kdim + k0 + c * 8;
            CP_ASYNC16(dst, src);
        }
    }
}

// ============================================================================
// GEMM inner compute (one K=32 chunk), 8 warps 2x4, warp 64x32
// ============================================================================
__device__ __forceinline__ void gemm_chunk(unsigned base, int wm, int wn,
                                           int g, int tig, float acc[4][4][4])
{
    const unsigned aho = base + 0 * TILEB;
    const unsigned alo = base + 1 * TILEB;
    const unsigned bho = base + 2 * TILEB;
    const unsigned blo = base + 3 * TILEB;

    #pragma unroll
    for (int s = 0; s < 2; s++) {
        unsigned aH[4][4], aL[4][4], bH[4][2], bL[4][2];
        #pragma unroll
        for (int mt = 0; mt < 4; mt++) {
            unsigned ro = (wm * 64 + mt * 16 + g) * TSB + (s * 16 + tig * 2) * 2;
            asm volatile("ld.shared.b32 %0, [%1];" : "=r"(aH[mt][0]) : "r"(aho + ro));
            asm volatile("ld.shared.b32 %0, [%1];" : "=r"(aH[mt][1]) : "r"(aho + ro + 8 * TSB));
            asm volatile("ld.shared.b32 %0, [%1];" : "=r"(aH[mt][2]) : "r"(aho + ro + 16));
            asm volatile("ld.shared.b32 %0, [%1];" : "=r"(aH[mt][3]) : "r"(aho + ro + 8 * TSB + 16));
            asm volatile("ld.shared.b32 %0, [%1];" : "=r"(aL[mt][0]) : "r"(alo + ro));
            asm volatile("ld.shared.b32 %0, [%1];" : "=r"(aL[mt][1]) : "r"(alo + ro + 8 * TSB));
            asm volatile("ld.shared.b32 %0, [%1];" : "=r"(aL[mt][2]) : "r"(alo + ro + 16));
            asm volatile("ld.shared.b32 %0, [%1];" : "=r"(aL[mt][3]) : "r"(alo + ro + 8 * TSB + 16));
        }
        #pragma unroll
        for (int nt = 0; nt < 4; nt++) {
            unsigned ro = (wn * 32 + nt * 8 + g) * TSB + (s * 16 + tig * 2) * 2;
            asm volatile("ld.shared.b32 %0, [%1];" : "=r"(bH[nt][0]) : "r"(bho + ro));
            asm volatile("ld.shared.b32 %0, [%1];" : "=r"(bH[nt][1]) : "r"(bho + ro + 16));
            asm volatile("ld.shared.b32 %0, [%1];" : "=r"(bL[nt][0]) : "r"(blo + ro));
            asm volatile("ld.shared.b32 %0, [%1];" : "=r"(bL[nt][1]) : "r"(blo + ro + 16));
        }
        #pragma unroll
        for (int mt = 0; mt < 4; mt++)
            #pragma unroll
            for (int nt = 0; nt < 4; nt++) {
                float* c4 = acc[mt][nt];
                mma_bf16(c4[0], c4[1], c4[2], c4[3],
                         aH[mt][0], aH[mt][1], aH[mt][2], aH[mt][3],
                         bH[nt][0], bH[nt][1]);
                mma_bf16(c4[0], c4[1], c4[2], c4[3],
                         aH[mt][0], aH[mt][1], aH[mt][2], aH[mt][3],
                         bL[nt][0], bL[nt][1]);
                mma_bf16(c4[0], c4[1], c4[2], c4[3],
                         aL[mt][0], aL[mt][1], aL[mt][2], aL[mt][3],
                         bH[nt][0], bH[nt][1]);
            }
    }
}

// ============================================================================
// Conv GEMM: 4-stage multistage pipeline, one barrier per chunk.
// ============================================================================
__global__ __launch_bounds__(256)
void conv_mma_kernel(const float* __restrict__ bq, const float* __restrict__ bk,
                     const float* __restrict__ bv)
{
    extern __shared__ __align__(128) char smem[];
    const int tid = threadIdx.x;
    const int wid = tid >> 5, lid = tid & 31;
    const int g = lid >> 2, tig = lid & 3;
    const int wm = wid & 1, wn = wid >> 1;

    const int tb = blockIdx.z;
    const int tensor = tb >> 3, b = tb & 7;
    const float* bias = (tensor == 0) ? bq : (tensor == 1) ? bk : bv;
    __nv_bfloat16* outh = (tensor == 0) ? g_Qh : (tensor == 1) ? g_Kh : g_Vh;
    __nv_bfloat16* outl = (tensor == 0) ? g_Ql : (tensor == 1) ? g_Kl : g_Vl;

    const int o0 = blockIdx.x * 128;
    const int p0 = blockIdx.y * 128;

    const __nv_bfloat16* Ah = g_Wh + (size_t)tensor * CDIM * KDIM + (size_t)o0 * KDIM;
    const __nv_bfloat16* Al = g_Wl + (size_t)tensor * CDIM * KDIM + (size_t)o0 * KDIM;
    const __nv_bfloat16* Bh = g_Bh + (size_t)tb * CDIM * KDIM + (size_t)p0 * KDIM;
    const __nv_bfloat16* Bl = g_Bl + (size_t)tb * CDIM * KDIM + (size_t)p0 * KDIM;

    const unsigned sb = smem_u32(smem);

    float acc[4][4][4];
    #pragma unroll
    for (int i = 0; i < 4; i++)
        #pragma unroll
        for (int j = 0; j < 4; j++)
            #pragma unroll
            for (int r = 0; r < 4; r++) acc[i][j][r] = 0.f;

    // prefetch 3 stages
    #pragma unroll
    for (int s = 0; s < NSTAGE - 1; s++) {
        stage_chunk(sb, s, Ah, Al, Bh, Bl, s * 32, tid, KDIM);
        CP_COMMIT();
    }

    for (int c = 0; c < NCHUNK; c++) {
        CP_WAIT2();            // stage c complete (<=2 groups outstanding)
        __syncthreads();       // all warps done with buffer (c-1)%4 = (c+3)%4
        if (c + NSTAGE - 1 < NCHUNK)
            stage_chunk(sb, (c + NSTAGE - 1) % NSTAGE, Ah, Al, Bh, Bl,
                        (c + NSTAGE - 1) * 32, tid, KDIM);
        CP_COMMIT();
        gemm_chunk(sb + (c % NSTAGE) * BUFB, wm, wn, g, tig, acc);
    }

    // epilogue: bf16 hi/lo split -> [b][o][p]
    #pragma unroll
    for (int mt = 0; mt < 4; mt++) {
        #pragma unroll
        for (int rr = 0; rr < 2; rr++) {
            int row = wm * 64 + mt * 16 + g + rr * 8;
            float bv_ = bias[o0 + row];
            size_t ro = ((size_t)b * CDIM + o0 + row) * CDIM + p0;
            #pragma unroll
            for (int nt = 0; nt < 4; nt++) {
                int col = wn * 32 + nt * 8 + tig * 2;
                float v0 = acc[mt][nt][rr * 2 + 0] + bv_;
                float v1 = acc[mt][nt][rr * 2 + 1] + bv_;
                __nv_bfloat162 h2 = __floats2bfloat162_rn(v0, v1);
                __nv_bfloat162 l2 = __floats2bfloat162_rn(v0 - __low2float(h2),
                                                          v1 - __high2float(h2));
                *(__nv_bfloat162*)(outh + ro + col) = h2;
                *(__nv_bfloat162*)(outl + ro + col) = l2;
            }
        }
    }
}

// ============================================================================
// Projection GEMM: same multistage pipeline, K=1024.
// ============================================================================
__global__ __launch_bounds__(256)
void proj_mma_kernel(const float* __restrict__ bo, float* __restrict__ out)
{
    extern __shared__ __align__(128) char smem[];
    const int tid = threadIdx.x;
    const int wid = tid >> 5, lid = tid & 31;
    const int g = lid >> 2, tig = lid & 3;
    const int wm = wid & 1, wn = wid >> 1;

    const int b  = blockIdx.z;
    const int c0 = blockIdx.x * 128;
    const int m0 = blockIdx.y * 128;

    const __nv_bfloat16* Ah = g_AOh + ((size_t)b * CDIM + c0) * CDIM;
    const __nv_bfloat16* Al = g_AOl + ((size_t)b * CDIM + c0) * CDIM;
    const __nv_bfloat16* Bh = g_Woh + (size_t)m0 * CDIM;
    const __nv_bfloat16* Bl = g_Wol + (size_t)m0 * CDIM;

    const unsigned sb = smem_u32(smem);

    float acc[4][4][4];
    #pragma unroll
    for (int i = 0; i < 4; i++)
        #pragma unroll
        for (int j = 0; j < 4; j++)
            #pragma unroll
            for (int r = 0; r < 4; r++) acc[i][j][r] = 0.f;

    #pragma unroll
    for (int s = 0; s < NSTAGE - 1; s++) {
        stage_chunk(sb, s, Ah, Al, Bh, Bl, s * 32, tid, CDIM);
        CP_COMMIT();
    }

    for (int c = 0; c < 32; c++) {
        CP_WAIT2();
        __syncthreads();
        if (c + NSTAGE - 1 < 32)
            stage_chunk(sb, (c + NSTAGE - 1) % NSTAGE, Ah, Al, Bh, Bl,
                        (c + NSTAGE - 1) * 32, tid, CDIM);
        CP_COMMIT();
        gemm_chunk(sb + (c % NSTAGE) * BUFB, wm, wn, g, tig, acc);
    }

    #pragma unroll
    for (int mt = 0; mt < 4; mt++) {
        #pragma unroll
        for (int rr = 0; rr < 2; rr++) {
            int row = wm * 64 + mt * 16 + g + rr * 8;
            float* orow = out + ((size_t)b * CDIM + c0 + row) * CDIM + m0;
            #pragma unroll
            for (int nt = 0; nt < 4; nt++) {
                int col = wn * 32 + nt * 8 + tig * 2;
                float2 vv;
                vv.x = acc[mt][nt][rr * 2 + 0] + bo[m0 + col];
                vv.y = acc[mt][nt][rr * 2 + 1] + bo[m0 + col + 1];
                *(float2*)(orow + col) = vv;
            }
        }
    }
}

// ============================================================================
// Attention via mma.sync, split bf16, flash-style online softmax (round-5).
// ============================================================================
#define ATS      144
#define ATT_QL   18432
#define ATT_BUF  36864
#define ATT_BUFSZ 36864
#define ATT_SMEM (ATT_BUF + 2 * ATT_BUFSZ)

__global__ __launch_bounds__(256)
void attn_mma_kernel(const int* __restrict__ mask)
{
    extern __shared__ __align__(128) char sm[];
    const unsigned sb = smem_u32(sm);
    const int tid = threadIdx.x, wid = tid >> 5, lane = tid & 31;
    const int bh = blockIdx.y, b = bh >> 4, head = bh & 15, hb = head * HD;
    const int t0 = blockIdx.x * 128;

    const size_t rowbase = (size_t)b * CDIM * CDIM + hb;

    for (int i = tid; i < 2048; i += 256) {
        int t = i >> 10, r = (i >> 3) & 127, c = i & 7;
        const __nv_bfloat16* src = (t ? g_Ql : g_Qh) + rowbase + (size_t)(t0 + r) * CDIM + c * 8;
        CP_ASYNC16(sb + t * ATT_QL + r * ATS + c * 16, src);
    }
    for (int i = tid; i < 2048; i += 256) {
        int t = i >> 9, r = (i >> 3) & 63, c = i & 7;
        const __nv_bfloat16* base = (t == 0) ? g_Kh : (t == 1) ? g_Kl
                                  : (t == 2) ? g_Vh : g_Vl;
        CP_ASYNC16(sb + ATT_BUF + t * 9216 + r * ATS + c * 16,
                   base + rowbase + (size_t)r * CDIM + c * 8);
    }
    CP_COMMIT();

    float oacc[8][4];
    #pragma unroll
    for (int i = 0; i < 8; i++)
        #pragma unroll
        for (int j = 0; j < 4; j++) oacc[i][j] = 0.f;
    float mrun0 = -1e30f, mrun1 = -1e30f, lrun0 = 0.f, lrun1 = 0.f;

    const int qrow = wid * 16 + (lane & 15);
    const unsigned qcoloff = ((lane >> 4) & 1) * 16;
    const unsigned kro = ((lane >> 4) & 1) * 8 + (lane & 7);
    const unsigned kco = ((lane >> 3) & 1) * 16;
    const unsigned vro = ((lane >> 3) & 1) * 8 + (lane & 7);
    const unsigned vco = ((lane >> 4) & 1) * 16;

    for (int s = 0; s < 16; s++) {
        __syncthreads();
        if (s + 1 < 16) {
            unsigned bufb = sb + ATT_BUF + ((s + 1) & 1) * ATT_BUFSZ;
            for (int i = tid; i < 2048; i += 256) {
                int t = i >> 9, r = (i >> 3) & 63, c = i & 7;
                const __nv_bfloat16* base = (t == 0) ? g_Kh : (t == 1) ? g_Kl
                                          : (t == 2) ? g_Vh : g_Vl;
                CP_ASYNC16(bufb + t * 9216 + r * ATS + c * 16,
                           base + rowbase + (size_t)((s + 1) * 64 + r) * CDIM + c * 8);
            }
        }
        CP_COMMIT();
        CP_WAIT1();
        __syncthreads();

        const unsigned kb = sb + ATT_BUF + (s & 1) * ATT_BUFSZ;

        float sacc[8][4];
        #pragma unroll
        for (int i = 0; i < 8; i++)
            #pragma unroll
            for (int j = 0; j < 4; j++) sacc[i][j] = 0.f;

        #pragma unroll
        for (int ks = 0; ks < 4; ks++) {
            unsigned qh[4], ql[4];
            unsigned qa = sb + qrow * ATS + ks * 32 + qcoloff;
            LDSM4(qh, qa);
            LDSM4(ql, qa + ATT_QL);
            #pragma unroll
            for (int gg = 0; gg < 4; gg++) {
                unsigned ka = kb + (gg * 16 + kro) * ATS + ks * 32 + kco;
                unsigned kh[4], kl[4];
                LDSM4(kh, ka);
                LDSM4(kl, ka + 9216);
                float* cA = sacc[2 * gg];
                float* cB = sacc[2 * gg + 1];
                mma_bf16(cA[0], cA[1], cA[2], cA[3], qh[0], qh[1], qh[2], qh[3], kh[0], kh[1]);
                mma_bf16(cA[0], cA[1], cA[2], cA[3], qh[0], qh[1], qh[2], qh[3], kl[0], kl[1]);
                mma_bf16(cA[0], cA[1], cA[2], cA[3], ql[0], ql[1], ql[2], ql[3], kh[0], kh[1]);
                mma_bf16(cB[0], cB[1], cB[2], cB[3], qh[0], qh[1], qh[2], qh[3], kh[2], kh[3]);
                mma_bf16(cB[0], cB[1], cB[2], cB[3], qh[0], qh[1], qh[2], qh[3], kl[2], kl[3]);
                mma_bf16(cB[0], cB[1], cB[2], cB[3], ql[0], ql[1], ql[2], ql[3], kh[2], kh[3]);
            }
        }

        const int r0 = t0 + wid * 16 + (lane >> 2);
        const int* mp = mask + (size_t)b * CDIM * CDIM + (size_t)r0 * CDIM
                        + s * 64 + (lane & 3) * 2;
        float mx0 = -1e30f, mx1 = -1e30f;
        #pragma unroll
        for (int nt = 0; nt < 8; nt++) {
            int2 m0 = *(const int2*)(mp + nt * 8);
            int2 m1 = *(const int2*)(mp + 8 * CDIM + nt * 8);
            float v0 = sacc[nt][0] * 0.125f; if (m0.x == 0) v0 = -1e9f;
            float v1 = sacc[nt][1] * 0.125f; if (m0.y == 0) v1 = -1e9f;
            float v2 = sacc[nt][2] * 0.125f; if (m1.x == 0) v2 = -1e9f;
            float v3 = sacc[nt][3] * 0.125f; if (m1.y == 0) v3 = -1e9f;
            sacc[nt][0] = v0; sacc[nt][1] = v1; sacc[nt][2] = v2; sacc[nt][3] = v3;
            mx0 = fmaxf(mx0, fmaxf(v0, v1));
            mx1 = fmaxf(mx1, fmaxf(v2, v3));
        }
        mx0 = fmaxf(mx0, __shfl_xor_sync(0xFFFFFFFFu, mx0, 1));
        mx0 = fmaxf(mx0, __shfl_xor_sync(0xFFFFFFFFu, mx0, 2));
        mx1 = fmaxf(mx1, __shfl_xor_sync(0xFFFFFFFFu, mx1, 1));
        mx1 = fmaxf(mx1, __shfl_xor_sync(0xFFFFFFFFu, mx1, 2));

        float mn0 = fmaxf(mrun0, mx0), mn1 = fmaxf(mrun1, mx1);
        float f0 = __expf(mrun0 - mn0), f1 = __expf(mrun1 - mn1);
        mrun0 = mn0; mrun1 = mn1;

        float sum0 = 0.f, sum1 = 0.f;
        #pragma unroll
        for (int nt = 0; nt < 8; nt++) {
            float p0 = __expf(sacc[nt][0] - mn0);
            float p1 = __expf(sacc[nt][1] - mn0);
            float p2 = __expf(sacc[nt][2] - mn1);
            float p3 = __expf(sacc[nt][3] - mn1);
            sacc[nt][0] = p0; sacc[nt][1] = p1; sacc[nt][2] = p2; sacc[nt][3] = p3;
            sum0 += p0 + p1; sum1 += p2 + p3;
        }
        sum0 += __shfl_xor_sync(0xFFFFFFFFu, sum0, 1);
        sum0 += __shfl_xor_sync(0xFFFFFFFFu, sum0, 2);
        sum1 += __shfl_xor_sync(0xFFFFFFFFu, sum1, 1);
        sum1 += __shfl_xor_sync(0xFFFFFFFFu, sum1, 2);
        lrun0 = lrun0 * f0 + sum0;
        lrun1 = lrun1 * f1 + sum1;

        #pragma unroll
        for (int nt = 0; nt < 8; nt++) {
            oacc[nt][0] *= f0; oacc[nt][1] *= f0;
            oacc[nt][2] *= f1; oacc[nt][3] *= f1;
        }

        #pragma unroll
        for (int ks = 0; ks < 4; ks++) {
            unsigned ah[4], al[4];
            #pragma unroll
            for (int h2i = 0; h2i < 2; h2i++) {
                float x0 = sacc[2 * ks + h2i][0], x1 = sacc[2 * ks + h2i][1];
                float x2 = sacc[2 * ks + h2i][2], x3 = sacc[2 * ks + h2i][3];
                __nv_bfloat162 hA = __floats2bfloat162_rn(x0, x1);
                __nv_bfloat162 hB = __floats2bfloat162_rn(x2, x3);
                ah[0 + 2 * h2i] = *(unsigned*)&hA;
                ah[1 + 2 * h2i] = *(unsigned*)&hB;
                __nv_bfloat162 lA = __floats2bfloat162_rn(x0 - __low2float(hA),
                                                          x1 - __high2float(hA));
                __nv_bfloat162 lB = __floats2bfloat162_rn(x2 - __low2float(hB),
                                                          x3 - __high2float(hB));
                al[0 + 2 * h2i] = *(unsigned*)&lA;
                al[1 + 2 * h2i] = *(unsigned*)&lB;
            }
            unsigned a0 = ah[0], a1 = ah[1], a2 = ah[2], a3 = ah[3];
            unsigned b0 = al[0], b1 = al[1], b2 = al[2], b3 = al[3];
            #pragma unroll
            for (int gg = 0; gg < 4; gg++) {
                unsigned va = kb + 2 * 9216 + (ks * 16 + vro) * ATS + gg * 32 + vco;
                unsigned vh[4], vl[4];
                LDSM4T(vh, va);
                LDSM4T(vl, va + 9216);
                float* cA = oacc[2 * gg];
                float* cB = oacc[2 * gg + 1];
                mma_bf16(cA[0], cA[1], cA[2], cA[3], a0, a1, a2, a3, vh[0], vh[1]);
                mma_bf16(cA[0], cA[1], cA[2], cA[3], a0, a1, a2, a3, vl[0], vl[1]);
                mma_bf16(cA[0], cA[1], cA[2], cA[3], b0, b1, b2, b3, vh[0], vh[1]);
                mma_bf16(cB[0], cB[1], cB[2], cB[3], a0, a1, a2, a3, vh[2], vh[3]);
                mma_bf16(cB[0], cB[1], cB[2], cB[3], a0, a1, a2, a3, vl[2], vl[3]);
                mma_bf16(cB[0], cB[1], cB[2], cB[3], b0, b1, b2, b3, vh[2], vh[3]);
            }
        }
    }

    float li0 = 1.f / lrun0, li1 = 1.f / lrun1;
    const int r0g = t0 + wid * 16 + (lane >> 2);
    const size_t ob = (size_t)b * CDIM * CDIM + hb;
    #pragma unroll
    for (int nt = 0; nt < 8; nt++) {
        int col = nt * 8 + (lane & 3) * 2;
        float v0 = oacc[nt][0] * li0, v1 = oacc[nt][1] * li0;
        __nv_bfloat162 h2 = __floats2bfloat162_rn(v0, v1);
        __nv_bfloat162 l2 = __floats2bfloat162_rn(v0 - __low2float(h2),
                                                  v1 - __high2float(h2));
        *(__nv_bfloat162*)(g_AOh + ob + (size_t)r0g * CDIM + col) = h2;
        *(__nv_bfloat162*)(g_AOl + ob + (size_t)r0g * CDIM + col) = l2;
        float v2 = oacc[nt][2] * li1, v3 = oacc[nt][3] * li1;
        __nv_bfloat162 h3 = __floats2bfloat162_rn(v2, v3);
        __nv_bfloat162 l3 = __floats2bfloat162_rn(v2 - __low2float(h3),
                                                  v3 - __high2float(h3));
        *(__nv_bfloat162*)(g_AOh + ob + (size_t)(r0g + 8) * CDIM + col) = h3;
        *(__nv_bfloat162*)(g_AOl + ob + (size_t)(r0g + 8) * CDIM + col) = l3;
    }
}

// ============================================================================
extern "C" void kernel_launch(void* const* d_in, const int* in_sizes, int n_in,
                              void* d_out, int out_size)
{
    const float* q    = (const float*)d_in[0];
    const float* k    = (const float*)d_in[1];
    const float* v    = (const float*)d_in[2];
    const float* Wq   = (const float*)d_in[3];
    const float* bq   = (const float*)d_in[4];
    const float* Wk   = (const float*)d_in[5];
    const float* bk   = (const float*)d_in[6];
    const float* Wv   = (const float*)d_in[7];
    const float* bv   = (const float*)d_in[8];
    const float* Wo   = (const float*)d_in[9];
    const float* bo   = (const float*)d_in[10];
    const int*   mask = (const int*)d_in[11];

    // 1) split weights (conv + Wo)
    wsplit_kernel<<<dim3(1024, 4), 256>>>(Wq, Wk, Wv, Wo);

    // 2) im2col with bf16 split
    im2col_kernel<<<dim3(8, 32, 24), 256>>>(q, k, v);

    // 3) conv GEMM, 4-stage multistage
    cudaFuncSetAttribute(conv_mma_kernel,
                         cudaFuncAttributeMaxDynamicSharedMemorySize, GSMEM);
    conv_mma_kernel<<<dim3(8, 8, 24), 256, GSMEM>>>(bq, bk, bv);

    // 4) attention
    cudaFuncSetAttribute(attn_mma_kernel,
                         cudaFuncAttributeMaxDynamicSharedMemorySize, ATT_SMEM);
    attn_mma_kernel<<<dim3(8, 128), 256, ATT_SMEM>>>(mask);

    // 5) projection GEMM, 4-stage multistage
    cudaFuncSetAttribute(proj_mma_kernel,
                         cudaFuncAttributeMaxDynamicSharedMemorySize, GSMEM);
    proj_mma_kernel<<<dim3(8, 8, 8), 256, GSMEM>>>(bo, (float*)d_out);
}